// round 1
// baseline (speedup 1.0000x reference)
#include <cuda_runtime.h>
#include <cuda_bf16.h>
#include <cstdint>

// ---------------------------------------------------------------------------
// MoE SwiGLU FFN (fp32), GB300 sm_103a
// Phase plan:
//   1. route   : gate logits -> softmax -> top2 -> per-expert token lists
//   2. offsets : exclusive prefix sum of counts
//   3. gather  : routed token rows -> contiguous g_xg
//   4. shared expert : GEMM1(w1), GEMM1(w3), swiglu, GEMM2 (store to out)
//   5. routed experts: grouped GEMM1 x2, swiglu*weight, grouped GEMM2 (atomicAdd)
// GEMM: 128x128x32 tiles, 256 threads, 8x8 microtile, packed fma.rn.f32x2.
// ---------------------------------------------------------------------------

#define DIMD 1024
#define HID  2752
#define NEXP 8
#define NTOK 8192         // B*S
#define CAP  8192         // per-expert worst-case rows
#define RT   16384        // total routed rows == 2*NTOK always (top-2 distinct)

// ------------------------- scratch (device globals) ------------------------
__device__ int   g_cnt[NEXP];
__device__ int   g_off[NEXP + 1];
__device__ int   g_tok[NEXP * CAP];
__device__ float g_wt [NEXP * CAP];
__device__ int   g_rowtok[RT];
__device__ float g_rowwt [RT];
__device__ float g_xg[(size_t)RT * DIMD];
__device__ float g_h [(size_t)RT * HID];
__device__ float g_g3[(size_t)RT * HID];

// ------------------------- small helpers -----------------------------------
__device__ __forceinline__ unsigned long long ffma2(unsigned long long a,
                                                    unsigned long long b,
                                                    unsigned long long c) {
    asm("fma.rn.f32x2 %0, %1, %2, %0;" : "+l"(c) : "l"(a), "l"(b));
    return c;
}
__device__ __forceinline__ unsigned long long pack2(float f) {
    unsigned long long r;
    asm("mov.b64 %0, {%1, %1};" : "=l"(r) : "r"(__float_as_uint(f)));
    return r;
}
__device__ __forceinline__ float f2lo(unsigned long long v) {
    return __uint_as_float((unsigned)(v & 0xffffffffu));
}
__device__ __forceinline__ float f2hi(unsigned long long v) {
    return __uint_as_float((unsigned)(v >> 32));
}

// ------------------------- phase kernels -----------------------------------
__global__ void zero_kernel() {
    if (threadIdx.x < NEXP) g_cnt[threadIdx.x] = 0;
}

__global__ void route_kernel(const float* __restrict__ x,
                             const float* __restrict__ gw) {
    int warp = (blockIdx.x * blockDim.x + threadIdx.x) >> 5;
    int lane = threadIdx.x & 31;
    if (warp >= NTOK) return;
    const float* xr = x + (size_t)warp * DIMD;
    float xv[32];
#pragma unroll
    for (int i = 0; i < 32; i++) xv[i] = xr[i * 32 + lane];

    float logit[NEXP];
#pragma unroll
    for (int e = 0; e < NEXP; e++) {
        const float* g = gw + e * DIMD;
        float s = 0.f;
#pragma unroll
        for (int i = 0; i < 32; i++) s += xv[i] * g[i * 32 + lane];
#pragma unroll
        for (int o = 16; o; o >>= 1) s += __shfl_xor_sync(0xffffffffu, s, o);
        logit[e] = s;
    }
    // softmax (fp32)
    float mx = logit[0];
#pragma unroll
    for (int e = 1; e < NEXP; e++) mx = fmaxf(mx, logit[e]);
    float p[NEXP], sum = 0.f;
#pragma unroll
    for (int e = 0; e < NEXP; e++) { p[e] = expf(logit[e] - mx); sum += p[e]; }
#pragma unroll
    for (int e = 0; e < NEXP; e++) p[e] /= sum;
    // top-2, first-occurrence tie-break (matches jax top_k)
    int i1 = 0;
#pragma unroll
    for (int e = 1; e < NEXP; e++) if (p[e] > p[i1]) i1 = e;
    int i2 = (i1 == 0) ? 1 : 0;
#pragma unroll
    for (int e = 0; e < NEXP; e++)
        if (e != i1 && e != i2 && p[e] > p[i2]) i2 = e;
    // jax picks i2 = first index attaining 2nd-largest; ensure ordering:
    // scan ascending, keep strict-greater -> first occurrence kept. Need the
    // initial candidate to be the smallest non-i1 index, done above.
    float d  = p[i1] + p[i2] + 1e-20f;
    float wa = p[i1] / d, wb = p[i2] / d;
    if (lane == 0) {
        int s1 = atomicAdd(&g_cnt[i1], 1);
        g_tok[i1 * CAP + s1] = warp; g_wt[i1 * CAP + s1] = wa;
        int s2 = atomicAdd(&g_cnt[i2], 1);
        g_tok[i2 * CAP + s2] = warp; g_wt[i2 * CAP + s2] = wb;
    }
}

__global__ void offsets_kernel() {
    if (threadIdx.x == 0) {
        int o = 0;
        for (int e = 0; e < NEXP; e++) { g_off[e] = o; o += g_cnt[e]; }
        g_off[NEXP] = o;
    }
}

__global__ void gather_kernel(const float* __restrict__ x) {
    int e = blockIdx.y, i = blockIdx.x;
    int cnt = g_off[e + 1] - g_off[e];
    if (i >= cnt) return;
    int r = g_off[e] + i;
    int t = g_tok[e * CAP + i];
    const float4* src = (const float4*)(x + (size_t)t * DIMD);
    float4* dst = (float4*)(g_xg + (size_t)r * DIMD);
    dst[threadIdx.x] = src[threadIdx.x];   // 256 threads x float4 = 1024 floats
    if (threadIdx.x == 0) { g_rowtok[r] = t; g_rowwt[r] = g_wt[e * CAP + i]; }
}

__global__ void swiglu_kernel(float* __restrict__ h,
                              const float* __restrict__ g3, int useWt) {
    int r = blockIdx.x;
    float w = useWt ? g_rowwt[r] : 1.0f;
    float4* hp = (float4*)(h + (size_t)r * HID);
    const float4* gp = (const float4*)(g3 + (size_t)r * HID);
    for (int c = threadIdx.x; c < HID / 4; c += blockDim.x) {
        float4 a = hp[c]; float4 b = gp[c];
        a.x = w * (a.x / (1.f + __expf(-a.x))) * b.x;
        a.y = w * (a.y / (1.f + __expf(-a.y))) * b.y;
        a.z = w * (a.z / (1.f + __expf(-a.z))) * b.z;
        a.w = w * (a.w / (1.f + __expf(-a.w))) * b.w;
        hp[c] = a;
    }
}

// ------------------------- generic grouped SGEMM ---------------------------
// C[m, n] = sum_k A[m, k] * B_e[n, k]     (A row-major [*,K], B row-major [N,K])
// mode bit0: grouped (rows per expert from g_off);  bit1: scatter-atomicAdd
//            via g_rowtok (C row = g_rowtok[m]).
#define TM 128
#define TN 128
#define BKK 32

__global__ __launch_bounds__(256, 2)
void gemm_kernel(const float* __restrict__ A, const float* __restrict__ B,
                 float* __restrict__ C, int N, int K, long long strideB,
                 int M0, int mode) {
    __shared__ float As[BKK][TM];
    __shared__ float Bs[BKK][TN];

    int e = blockIdx.z;
    int rs, re;
    if (mode & 1) { rs = g_off[e]; re = g_off[e + 1]; }
    else          { rs = 0;        re = M0; }
    int m0 = rs + blockIdx.y * TM;
    if (m0 >= re) return;
    const float* Be = B + (long long)e * strideB;
    int n0 = blockIdx.x * TN;

    int tid = threadIdx.x;
    int lr = tid >> 3;
    int lc = (tid & 7) << 2;
    int tx = tid & 15, ty = tid >> 4;

    unsigned long long acc[4][8];
#pragma unroll
    for (int i = 0; i < 4; i++)
#pragma unroll
        for (int j = 0; j < 8; j++) acc[i][j] = 0ull;

    for (int k0 = 0; k0 < K; k0 += BKK) {
#pragma unroll
        for (int p = 0; p < 4; p++) {
            int m = lr + p * 32;
            int gr = m0 + m;
            float4 v = make_float4(0.f, 0.f, 0.f, 0.f);
            if (gr < re) v = *(const float4*)(A + (size_t)gr * K + k0 + lc);
            As[lc + 0][m] = v.x; As[lc + 1][m] = v.y;
            As[lc + 2][m] = v.z; As[lc + 3][m] = v.w;
        }
#pragma unroll
        for (int p = 0; p < 4; p++) {
            int nn = lr + p * 32;
            int gn = n0 + nn;
            float4 v = make_float4(0.f, 0.f, 0.f, 0.f);
            if (gn < N) v = *(const float4*)(Be + (size_t)gn * K + k0 + lc);
            Bs[lc + 0][nn] = v.x; Bs[lc + 1][nn] = v.y;
            Bs[lc + 2][nn] = v.z; Bs[lc + 3][nn] = v.w;
        }
        __syncthreads();
#pragma unroll
        for (int kk = 0; kk < BKK; kk++) {
            double2 a0 = *(const double2*)&As[kk][ty * 4];
            double2 a1 = *(const double2*)&As[kk][64 + ty * 4];
            unsigned long long av[4];
            av[0] = __double_as_longlong(a0.x);
            av[1] = __double_as_longlong(a0.y);
            av[2] = __double_as_longlong(a1.x);
            av[3] = __double_as_longlong(a1.y);
            float4 b0 = *(const float4*)&Bs[kk][tx * 4];
            float4 b1 = *(const float4*)&Bs[kk][64 + tx * 4];
            float bf[8] = {b0.x, b0.y, b0.z, b0.w, b1.x, b1.y, b1.z, b1.w};
#pragma unroll
            for (int j = 0; j < 8; j++) {
                unsigned long long bb = pack2(bf[j]);
#pragma unroll
                for (int ip = 0; ip < 4; ip++)
                    acc[ip][j] = ffma2(av[ip], bb, acc[ip][j]);
            }
        }
        __syncthreads();
    }

    // epilogue
#pragma unroll
    for (int ip = 0; ip < 4; ip++) {
        int rbase = (ip < 2) ? (ty * 4 + 2 * ip) : (64 + ty * 4 + 2 * (ip - 2));
#pragma unroll
        for (int h = 0; h < 2; h++) {
            int gr = m0 + rbase + h;
            if (gr >= re) continue;
            size_t crow = (mode & 2) ? (size_t)g_rowtok[gr] * N
                                     : (size_t)gr * N;
#pragma unroll
            for (int j = 0; j < 8; j++) {
                int col = n0 + ((j < 4) ? tx * 4 + j : 64 + tx * 4 + (j - 4));
                if (col < N) {
                    unsigned long long v = acc[ip][j];
                    float f = (h == 0) ? f2lo(v) : f2hi(v);
                    if (mode & 2) atomicAdd(&C[crow + col], f);
                    else          C[crow + col] = f;
                }
            }
        }
    }
}

// ------------------------- launch ------------------------------------------
extern "C" void kernel_launch(void* const* d_in, const int* in_sizes, int n_in,
                              void* d_out, int out_size) {
    const float* x      = (const float*)d_in[0];
    const float* gate_w = (const float*)d_in[1];
    const float* w1     = (const float*)d_in[2];
    const float* w3     = (const float*)d_in[3];
    const float* w2     = (const float*)d_in[4];
    const float* sw1    = (const float*)d_in[5];
    const float* sw3    = (const float*)d_in[6];
    const float* sw2    = (const float*)d_in[7];
    float* out = (float*)d_out;

    float *hP = nullptr, *g3P = nullptr, *xgP = nullptr;
    cudaGetSymbolAddress((void**)&hP,  g_h);
    cudaGetSymbolAddress((void**)&g3P, g_g3);
    cudaGetSymbolAddress((void**)&xgP, g_xg);

    zero_kernel<<<1, 32>>>();
    route_kernel<<<NTOK / 8, 256>>>(x, gate_w);
    offsets_kernel<<<1, 1>>>();
    gather_kernel<<<dim3(CAP, NEXP), 256>>>(x);

    const int NT_H = (HID + TN - 1) / TN;   // 22
    const int NT_D = DIMD / TN;             // 8
    const int MT_T = NTOK / TM;             // 64
    const int MT_C = CAP / TM;              // 64 (per-expert capacity tiles)

    // ---- shared expert (writes every element of out; out is poisoned) ----
    gemm_kernel<<<dim3(NT_H, MT_T, 1), 256>>>(x, sw1, hP,  HID, DIMD, 0, NTOK, 0);
    gemm_kernel<<<dim3(NT_H, MT_T, 1), 256>>>(x, sw3, g3P, HID, DIMD, 0, NTOK, 0);
    swiglu_kernel<<<NTOK, 256>>>(hP, g3P, 0);
    gemm_kernel<<<dim3(NT_D, MT_T, 1), 256>>>(hP, sw2, out, DIMD, HID, 0, NTOK, 0);

    // ---- routed experts (grouped; weight folded into hidden; atomic add) --
    gemm_kernel<<<dim3(NT_H, MT_C, NEXP), 256>>>(xgP, w1, hP,  HID, DIMD,
                                                 (long long)HID * DIMD, 0, 1);
    gemm_kernel<<<dim3(NT_H, MT_C, NEXP), 256>>>(xgP, w3, g3P, HID, DIMD,
                                                 (long long)HID * DIMD, 0, 1);
    swiglu_kernel<<<RT, 256>>>(hP, g3P, 1);
    gemm_kernel<<<dim3(NT_D, MT_C, NEXP), 256>>>(hP, w2, out, DIMD, HID,
                                                 (long long)DIMD * HID, 0, 3);
}

// round 3
// speedup vs baseline: 2.6499x; 2.6499x over previous
#include <cuda_runtime.h>
#include <cuda_bf16.h>
#include <cstdint>

// ---------------------------------------------------------------------------
// MoE SwiGLU FFN, GB300 (PTX target sm_103 plain -> no tcgen05; use HMMA
// mma.sync.m16n8k16 bf16 with 3-pass fp32 split: C = Ahi*Bhi + Ahi*Blo + Alo*Bhi.
// Pipeline: route -> cvt(hi/lo) -> gather -> GEMM1(w1), GEMM1(w3), swiglu,
// GEMM2(w2) for shared + routed experts (routed weight folded into swiglu,
// routed GEMM2 atomicAdds onto shared-expert output).
// GEMM: 128x128 CTA tile, TK=32, 3-stage cp.async, 8 warps (2x4), warp tile
// 64x32, XOR-swizzled smem for conflict-free ldmatrix.
// ---------------------------------------------------------------------------

#define DIMD 1024
#define HID  2752
#define NEXP 8
#define NTOK 8192
#define CAP  8192
#define RT   16384
#define TMg  128
#define TNg  128
#define TKg  32
#define STG  3

typedef __nv_bfloat16 bf16;

// ------------------------- scratch (device globals) ------------------------
__device__ int   g_cnt[NEXP];
__device__ int   g_off[NEXP + 1];
__device__ int   g_tok[NEXP * CAP];
__device__ float g_wt [NEXP * CAP];
__device__ int   g_rowtok[RT];
__device__ float g_rowwt [RT];

__device__ bf16 g_xhi [(size_t)NTOK * DIMD];
__device__ bf16 g_xlo [(size_t)NTOK * DIMD];
__device__ bf16 g_gxhi[(size_t)(RT + TMg) * DIMD];
__device__ bf16 g_gxlo[(size_t)(RT + TMg) * DIMD];
__device__ float g_h  [(size_t)RT * HID];
__device__ float g_g3 [(size_t)RT * HID];
__device__ bf16 g_hhi[(size_t)(RT + TMg) * HID];
__device__ bf16 g_hlo[(size_t)(RT + TMg) * HID];

__device__ bf16 g_w1hi[(size_t)NEXP * HID * DIMD];
__device__ bf16 g_w1lo[(size_t)NEXP * HID * DIMD];
__device__ bf16 g_w3hi[(size_t)NEXP * HID * DIMD];
__device__ bf16 g_w3lo[(size_t)NEXP * HID * DIMD];
__device__ bf16 g_w2hi[(size_t)NEXP * DIMD * HID];
__device__ bf16 g_w2lo[(size_t)NEXP * DIMD * HID];
__device__ bf16 g_s1hi[(size_t)HID * DIMD];
__device__ bf16 g_s1lo[(size_t)HID * DIMD];
__device__ bf16 g_s3hi[(size_t)HID * DIMD];
__device__ bf16 g_s3lo[(size_t)HID * DIMD];
__device__ bf16 g_s2hi[(size_t)DIMD * HID];
__device__ bf16 g_s2lo[(size_t)DIMD * HID];

// ------------------------- PTX helpers -------------------------------------
__device__ __forceinline__ uint32_t smem_u32(const void* p) {
    uint32_t a;
    asm("{ .reg .u64 t; cvta.to.shared.u64 t, %1; cvt.u32.u64 %0, t; }"
        : "=r"(a) : "l"(p));
    return a;
}
__device__ __forceinline__ void cpa16(uint32_t dst, const void* src, uint32_t sz) {
    asm volatile("cp.async.cg.shared.global [%0], [%1], 16, %2;"
                 :: "r"(dst), "l"(src), "r"(sz));
}
#define CP_COMMIT() asm volatile("cp.async.commit_group;" ::: "memory")
#define CP_WAIT(n)  asm volatile("cp.async.wait_group %0;" :: "n"(n) : "memory")

__device__ __forceinline__ void ldsm4(uint32_t* r, uint32_t addr) {
    asm volatile("ldmatrix.sync.aligned.m8n8.x4.shared.b16 {%0,%1,%2,%3}, [%4];"
                 : "=r"(r[0]), "=r"(r[1]), "=r"(r[2]), "=r"(r[3]) : "r"(addr));
}
__device__ __forceinline__ void ldsm2(uint32_t* r, uint32_t addr) {
    asm volatile("ldmatrix.sync.aligned.m8n8.x2.shared.b16 {%0,%1}, [%2];"
                 : "=r"(r[0]), "=r"(r[1]) : "r"(addr));
}
__device__ __forceinline__ void mma16816(float* d, const uint32_t* a,
                                         const uint32_t* b) {
    asm volatile("mma.sync.aligned.m16n8k16.row.col.f32.bf16.bf16.f32 "
                 "{%0,%1,%2,%3}, {%4,%5,%6,%7}, {%8,%9}, {%0,%1,%2,%3};"
                 : "+f"(d[0]), "+f"(d[1]), "+f"(d[2]), "+f"(d[3])
                 : "r"(a[0]), "r"(a[1]), "r"(a[2]), "r"(a[3]),
                   "r"(b[0]), "r"(b[1]));
}
// swizzled smem byte offset for row-major [128][32] bf16, 64B rows split into
// 4 x 16B chunks; chunk' = chunk ^ ((row>>1)&3)  (conflict-free ldmatrix)
__device__ __forceinline__ uint32_t swz(int row, int chunk) {
    return (uint32_t)(row * 64 + ((chunk ^ ((row >> 1) & 3)) << 4));
}

// ------------------------- phase kernels -----------------------------------
__global__ void zero_kernel() {
    if (threadIdx.x < NEXP) g_cnt[threadIdx.x] = 0;
}

__global__ void route_kernel(const float* __restrict__ x,
                             const float* __restrict__ gw) {
    int warp = (blockIdx.x * blockDim.x + threadIdx.x) >> 5;
    int lane = threadIdx.x & 31;
    if (warp >= NTOK) return;
    const float* xr = x + (size_t)warp * DIMD;
    float xv[32];
#pragma unroll
    for (int i = 0; i < 32; i++) xv[i] = xr[i * 32 + lane];
    float logit[NEXP];
#pragma unroll
    for (int e = 0; e < NEXP; e++) {
        const float* g = gw + e * DIMD;
        float s = 0.f;
#pragma unroll
        for (int i = 0; i < 32; i++) s += xv[i] * g[i * 32 + lane];
#pragma unroll
        for (int o = 16; o; o >>= 1) s += __shfl_xor_sync(0xffffffffu, s, o);
        logit[e] = s;
    }
    float mx = logit[0];
#pragma unroll
    for (int e = 1; e < NEXP; e++) mx = fmaxf(mx, logit[e]);
    float p[NEXP], sum = 0.f;
#pragma unroll
    for (int e = 0; e < NEXP; e++) { p[e] = expf(logit[e] - mx); sum += p[e]; }
#pragma unroll
    for (int e = 0; e < NEXP; e++) p[e] /= sum;
    int i1 = 0;
#pragma unroll
    for (int e = 1; e < NEXP; e++) if (p[e] > p[i1]) i1 = e;
    int i2 = (i1 == 0) ? 1 : 0;
#pragma unroll
    for (int e = 0; e < NEXP; e++)
        if (e != i1 && e != i2 && p[e] > p[i2]) i2 = e;
    float d  = p[i1] + p[i2] + 1e-20f;
    float wa = p[i1] / d, wb = p[i2] / d;
    if (lane == 0) {
        int s1 = atomicAdd(&g_cnt[i1], 1);
        g_tok[i1 * CAP + s1] = warp; g_wt[i1 * CAP + s1] = wa;
        int s2 = atomicAdd(&g_cnt[i2], 1);
        g_tok[i2 * CAP + s2] = warp; g_wt[i2 * CAP + s2] = wb;
    }
}

__global__ void offsets_kernel() {
    if (threadIdx.x == 0) {
        int o = 0;
        for (int e = 0; e < NEXP; e++) { g_off[e] = o; o += g_cnt[e]; }
        g_off[NEXP] = o;
    }
}

// fp32 -> bf16 hi/lo split, vectorized by 4
__global__ void cvt_kernel(const float4* __restrict__ src,
                           uint2* __restrict__ hi, uint2* __restrict__ lo,
                           int n4) {
    int i = blockIdx.x * blockDim.x + threadIdx.x;
    if (i >= n4) return;
    float4 v = src[i];
    bf16 h0 = __float2bfloat16(v.x), h1 = __float2bfloat16(v.y);
    bf16 h2 = __float2bfloat16(v.z), h3 = __float2bfloat16(v.w);
    bf16 l0 = __float2bfloat16(v.x - __bfloat162float(h0));
    bf16 l1 = __float2bfloat16(v.y - __bfloat162float(h1));
    bf16 l2 = __float2bfloat16(v.z - __bfloat162float(h2));
    bf16 l3 = __float2bfloat16(v.w - __bfloat162float(h3));
    __nv_bfloat162 ha(h0, h1), hb(h2, h3), la(l0, l1), lb(l2, l3);
    uint2 H, L;
    H.x = *(const unsigned*)&ha; H.y = *(const unsigned*)&hb;
    L.x = *(const unsigned*)&la; L.y = *(const unsigned*)&lb;
    hi[i] = H; lo[i] = L;
}

__global__ void gather_kernel() {
    int e = blockIdx.y, i = blockIdx.x;
    int cnt = g_off[e + 1] - g_off[e];
    if (i >= cnt) return;
    int r = g_off[e] + i;
    int t = g_tok[e * CAP + i];
    const uint4* sh = (const uint4*)(g_xhi + (size_t)t * DIMD);
    const uint4* sl = (const uint4*)(g_xlo + (size_t)t * DIMD);
    uint4* dh = (uint4*)(g_gxhi + (size_t)r * DIMD);
    uint4* dl = (uint4*)(g_gxlo + (size_t)r * DIMD);
    int c = threadIdx.x;                 // 128 threads, 128 uint4/row
    dh[c] = sh[c]; dl[c] = sl[c];
    if (c == 0) { g_rowtok[r] = t; g_rowwt[r] = g_wt[e * CAP + i]; }
}

__global__ void swiglu_kernel(int useWt) {
    int r = blockIdx.x;
    float w = useWt ? g_rowwt[r] : 1.0f;
    const float4* hp = (const float4*)(g_h  + (size_t)r * HID);
    const float4* gp = (const float4*)(g_g3 + (size_t)r * HID);
    uint2* oh = (uint2*)(g_hhi + (size_t)r * HID);
    uint2* ol = (uint2*)(g_hlo + (size_t)r * HID);
    for (int c = threadIdx.x; c < HID / 4; c += blockDim.x) {
        float4 a = hp[c]; float4 b = gp[c];
        float v0 = w * (a.x / (1.f + __expf(-a.x))) * b.x;
        float v1 = w * (a.y / (1.f + __expf(-a.y))) * b.y;
        float v2 = w * (a.z / (1.f + __expf(-a.z))) * b.z;
        float v3 = w * (a.w / (1.f + __expf(-a.w))) * b.w;
        bf16 h0 = __float2bfloat16(v0), h1 = __float2bfloat16(v1);
        bf16 h2 = __float2bfloat16(v2), h3 = __float2bfloat16(v3);
        bf16 l0 = __float2bfloat16(v0 - __bfloat162float(h0));
        bf16 l1 = __float2bfloat16(v1 - __bfloat162float(h1));
        bf16 l2 = __float2bfloat16(v2 - __bfloat162float(h2));
        bf16 l3 = __float2bfloat16(v3 - __bfloat162float(h3));
        __nv_bfloat162 ha(h0, h1), hb(h2, h3), la(l0, l1), lb(l2, l3);
        uint2 H, L;
        H.x = *(const unsigned*)&ha; H.y = *(const unsigned*)&hb;
        L.x = *(const unsigned*)&la; L.y = *(const unsigned*)&lb;
        oh[c] = H; ol[c] = L;
    }
}

// ------------------------- HMMA grouped GEMM -------------------------------
// C[m,n] = sum_k Ahi*Bhi + Ahi*Blo + Alo*Bhi  (A row-major [*,K], B [N,K])
// mode bit0: grouped rows per expert (g_off); bit1: atomicAdd scatter via
// g_rowtok. Tile 128x128x32, 3-stage cp.async, 8 warps (2m x 4n), wtile 64x32.
__global__ __launch_bounds__(256, 2)
void hmma_gemm(const bf16* __restrict__ Ahi, const bf16* __restrict__ Alo,
               const bf16* __restrict__ Bhi, const bf16* __restrict__ Blo,
               float* __restrict__ C, int N, int K, long long strideB,
               int M0, int mode) {
    __shared__ __align__(1024) char smc[STG * 16384];
    uint32_t sb = smem_u32(smc);

    int e = blockIdx.z;
    int rs, re;
    if (mode & 1) { rs = g_off[e]; re = g_off[e + 1]; }
    else          { rs = 0;        re = M0; }
    int m0 = rs + blockIdx.y * TMg;
    if (m0 >= re) return;
    const bf16* bhi = Bhi + (size_t)e * strideB;
    const bf16* blo = Blo + (size_t)e * strideB;
    int n0 = blockIdx.x * TNg;

    int tid = threadIdx.x;
    int wid = tid >> 5, lane = tid & 31;
    int wm = wid & 1, wn = wid >> 1;

    const int KN = K / TKg;
    const int nch = 3 * KN;

    auto load_chunk = [&](int ch, int stage) {
        int p = (ch >= 2 * KN) ? 2 : (ch >= KN ? 1 : 0);
        int k0 = (ch - p * KN) * TKg;
        const bf16* Ap = (p == 2) ? Alo : Ahi;
        const bf16* Bp = (p == 1) ? blo : bhi;
        uint32_t sA = sb + stage * 16384;
        uint32_t sB = sA + 8192;
#pragma unroll
        for (int t = 0; t < 2; t++) {
            int u = tid + t * 256;
            int row = u >> 2, c = u & 3;
            int gr = m0 + row;
            int grc = (gr < re) ? gr : m0;
            const char* src = (const char*)(Ap + (size_t)grc * K + k0 + c * 8);
            cpa16(sA + swz(row, c), src, (gr < re) ? 16u : 0u);
        }
#pragma unroll
        for (int t = 0; t < 2; t++) {
            int u = tid + t * 256;
            int row = u >> 2, c = u & 3;
            int gn = n0 + row;
            int gnc = (gn < N) ? gn : 0;
            const char* src = (const char*)(Bp + (size_t)gnc * K + k0 + c * 8);
            cpa16(sB + swz(row, c), src, (gn < N) ? 16u : 0u);
        }
        CP_COMMIT();
    };

#pragma unroll
    for (int s = 0; s < STG - 1; s++) load_chunk(s, s);

    float acc[4][4][4];
#pragma unroll
    for (int a = 0; a < 4; a++)
#pragma unroll
        for (int b = 0; b < 4; b++)
#pragma unroll
            for (int c = 0; c < 4; c++) acc[a][b][c] = 0.f;

    for (int i = 0; i < nch; i++) {
        if (i + STG - 1 < nch) load_chunk(i + STG - 1, (i + STG - 1) % STG);
        else                   CP_COMMIT();
        CP_WAIT(STG - 1);
        __syncthreads();
        uint32_t sA = sb + (i % STG) * 16384;
        uint32_t sB = sA + 8192;
#pragma unroll
        for (int ks = 0; ks < 2; ks++) {
            uint32_t af[4][4], bfr[4][2];
#pragma unroll
            for (int mi = 0; mi < 4; mi++) {
                int row = wm * 64 + mi * 16 + (lane & 15);
                int c = ks * 2 + (lane >> 4);
                ldsm4(af[mi], sA + swz(row, c));
            }
#pragma unroll
            for (int nj = 0; nj < 4; nj++) {
                int row = wn * 32 + nj * 8 + (lane & 7);
                int c = ks * 2 + ((lane >> 3) & 1);
                ldsm2(bfr[nj], sB + swz(row, c));
            }
#pragma unroll
            for (int mi = 0; mi < 4; mi++)
#pragma unroll
                for (int nj = 0; nj < 4; nj++)
                    mma16816(acc[mi][nj], af[mi], bfr[nj]);
        }
        __syncthreads();
    }

    // epilogue
#pragma unroll
    for (int mi = 0; mi < 4; mi++) {
        int r0 = m0 + wm * 64 + mi * 16 + (lane >> 2);
#pragma unroll
        for (int h = 0; h < 2; h++) {
            int gr = r0 + h * 8;
            if (gr >= re) continue;
            size_t crow = (mode & 2) ? (size_t)g_rowtok[gr] * N
                                     : (size_t)gr * N;
#pragma unroll
            for (int nj = 0; nj < 4; nj++) {
                int col = n0 + wn * 32 + nj * 8 + (lane & 3) * 2;
                if (col >= N) continue;
                float v0 = acc[mi][nj][h * 2 + 0];
                float v1 = acc[mi][nj][h * 2 + 1];
                if (mode & 2) {
                    atomicAdd(&C[crow + col], v0);
                    atomicAdd(&C[crow + col + 1], v1);
                } else {
                    *(float2*)&C[crow + col] = make_float2(v0, v1);
                }
            }
        }
    }
}

// ------------------------- launch ------------------------------------------
static void cvt(const void* src, void* hi, void* lo, size_t n) {
    int n4 = (int)(n / 4);
    cvt_kernel<<<(n4 + 255) / 256, 256>>>((const float4*)src, (uint2*)hi,
                                          (uint2*)lo, n4);
}

extern "C" void kernel_launch(void* const* d_in, const int* in_sizes, int n_in,
                              void* d_out, int out_size) {
    const float* x      = (const float*)d_in[0];
    const float* gate_w = (const float*)d_in[1];
    const float* w1     = (const float*)d_in[2];
    const float* w3     = (const float*)d_in[3];
    const float* w2     = (const float*)d_in[4];
    const float* sw1    = (const float*)d_in[5];
    const float* sw3    = (const float*)d_in[6];
    const float* sw2    = (const float*)d_in[7];
    float* out = (float*)d_out;

    void *xhi, *xlo, *gxhi, *gxlo, *hP, *g3P, *hhi, *hlo;
    void *w1h, *w1l, *w3h, *w3l, *w2h, *w2l;
    void *s1h, *s1l, *s3h, *s3l, *s2h, *s2l;
    cudaGetSymbolAddress(&xhi, g_xhi);   cudaGetSymbolAddress(&xlo, g_xlo);
    cudaGetSymbolAddress(&gxhi, g_gxhi); cudaGetSymbolAddress(&gxlo, g_gxlo);
    cudaGetSymbolAddress(&hP, g_h);      cudaGetSymbolAddress(&g3P, g_g3);
    cudaGetSymbolAddress(&hhi, g_hhi);   cudaGetSymbolAddress(&hlo, g_hlo);
    cudaGetSymbolAddress(&w1h, g_w1hi);  cudaGetSymbolAddress(&w1l, g_w1lo);
    cudaGetSymbolAddress(&w3h, g_w3hi);  cudaGetSymbolAddress(&w3l, g_w3lo);
    cudaGetSymbolAddress(&w2h, g_w2hi);  cudaGetSymbolAddress(&w2l, g_w2lo);
    cudaGetSymbolAddress(&s1h, g_s1hi);  cudaGetSymbolAddress(&s1l, g_s1lo);
    cudaGetSymbolAddress(&s3h, g_s3hi);  cudaGetSymbolAddress(&s3l, g_s3lo);
    cudaGetSymbolAddress(&s2h, g_s2hi);  cudaGetSymbolAddress(&s2l, g_s2lo);

    zero_kernel<<<1, 32>>>();
    route_kernel<<<NTOK / 8, 256>>>(x, gate_w);
    offsets_kernel<<<1, 1>>>();

    cvt(x,   xhi, xlo, (size_t)NTOK * DIMD);
    gather_kernel<<<dim3(CAP, NEXP), 128>>>();
    cvt(w1,  w1h, w1l, (size_t)NEXP * HID * DIMD);
    cvt(w3,  w3h, w3l, (size_t)NEXP * HID * DIMD);
    cvt(w2,  w2h, w2l, (size_t)NEXP * DIMD * HID);
    cvt(sw1, s1h, s1l, (size_t)HID * DIMD);
    cvt(sw3, s3h, s3l, (size_t)HID * DIMD);
    cvt(sw2, s2h, s2l, (size_t)DIMD * HID);

    const int NT_H = (HID + TNg - 1) / TNg;   // 22
    const int NT_D = DIMD / TNg;              // 8
    const int MT_T = NTOK / TMg;              // 64
    const int MT_C = CAP / TMg;               // 64

    // ---- shared expert ----
    hmma_gemm<<<dim3(NT_H, MT_T, 1), 256>>>(
        (const bf16*)xhi, (const bf16*)xlo, (const bf16*)s1h, (const bf16*)s1l,
        (float*)hP, HID, DIMD, 0, NTOK, 0);
    hmma_gemm<<<dim3(NT_H, MT_T, 1), 256>>>(
        (const bf16*)xhi, (const bf16*)xlo, (const bf16*)s3h, (const bf16*)s3l,
        (float*)g3P, HID, DIMD, 0, NTOK, 0);
    swiglu_kernel<<<NTOK, 256>>>(0);
    hmma_gemm<<<dim3(NT_D, MT_T, 1), 256>>>(
        (const bf16*)hhi, (const bf16*)hlo, (const bf16*)s2h, (const bf16*)s2l,
        out, DIMD, HID, 0, NTOK, 0);

    // ---- routed experts ----
    hmma_gemm<<<dim3(NT_H, MT_C, NEXP), 256>>>(
        (const bf16*)gxhi, (const bf16*)gxlo, (const bf16*)w1h, (const bf16*)w1l,
        (float*)hP, HID, DIMD, (long long)HID * DIMD, 0, 1);
    hmma_gemm<<<dim3(NT_H, MT_C, NEXP), 256>>>(
        (const bf16*)gxhi, (const bf16*)gxlo, (const bf16*)w3h, (const bf16*)w3l,
        (float*)g3P, HID, DIMD, (long long)HID * DIMD, 0, 1);
    swiglu_kernel<<<RT, 256>>>(1);
    hmma_gemm<<<dim3(NT_D, MT_C, NEXP), 256>>>(
        (const bf16*)hhi, (const bf16*)hlo, (const bf16*)w2h, (const bf16*)w2l,
        out, DIMD, HID, (long long)DIMD * HID, 0, 3);
}

// round 4
// speedup vs baseline: 2.6913x; 1.0156x over previous
#include <cuda_runtime.h>
#include <cuda_bf16.h>
#include <cstdint>

// ---------------------------------------------------------------------------
// MoE SwiGLU FFN, GB300 (plain sm_103 PTX target -> HMMA mma.sync.m16n8k16).
// 3-pass bf16 split: C = Ahi*Bhi + Ahi*Blo + Alo*Bhi  (fp32 accumulate).
// w1/w3 rows INTERLEAVED in the converted weight buffer so each mma thread's
// float2 = (h_j, g3_j) -> SwiGLU fused into the GEMM epilogue (writes bf16
// hi/lo hidden activations directly; no fp32 intermediate round-trip).
// Routed top-2 weight folded into the fused epilogue; routed GEMM2 atomicAdds
// onto the shared-expert output.
// ---------------------------------------------------------------------------

#define DIMD 1024
#define HID  2752
#define NEXP 8
#define NTOK 8192
#define CAP  8192
#define RT   16384
#define TMg  128
#define TNg  128
#define TKg  32
#define STG  3

typedef __nv_bfloat16 bf16;

// ------------------------- scratch (device globals) ------------------------
__device__ int   g_cnt[NEXP];
__device__ int   g_off[NEXP + 1];
__device__ int   g_tok[NEXP * CAP];
__device__ float g_wt [NEXP * CAP];
__device__ int   g_rowtok[RT];
__device__ float g_rowwt [RT];

__device__ bf16 g_xhi [(size_t)NTOK * DIMD];
__device__ bf16 g_xlo [(size_t)NTOK * DIMD];
__device__ bf16 g_gxhi[(size_t)(RT + TMg) * DIMD];
__device__ bf16 g_gxlo[(size_t)(RT + TMg) * DIMD];
__device__ bf16 g_hhi [(size_t)(RT + TMg) * HID];
__device__ bf16 g_hlo [(size_t)(RT + TMg) * HID];

// interleaved [w1 row j ; w3 row j] -> rows 2j, 2j+1
__device__ bf16 g_w13hi[(size_t)NEXP * 2 * HID * DIMD];
__device__ bf16 g_w13lo[(size_t)NEXP * 2 * HID * DIMD];
__device__ bf16 g_w2hi [(size_t)NEXP * DIMD * HID];
__device__ bf16 g_w2lo [(size_t)NEXP * DIMD * HID];
__device__ bf16 g_s13hi[(size_t)2 * HID * DIMD];
__device__ bf16 g_s13lo[(size_t)2 * HID * DIMD];
__device__ bf16 g_s2hi [(size_t)DIMD * HID];
__device__ bf16 g_s2lo [(size_t)DIMD * HID];

// ------------------------- PTX helpers -------------------------------------
__device__ __forceinline__ uint32_t smem_u32(const void* p) {
    uint32_t a;
    asm("{ .reg .u64 t; cvta.to.shared.u64 t, %1; cvt.u32.u64 %0, t; }"
        : "=r"(a) : "l"(p));
    return a;
}
__device__ __forceinline__ void cpa16(uint32_t dst, const void* src, uint32_t sz) {
    asm volatile("cp.async.cg.shared.global [%0], [%1], 16, %2;"
                 :: "r"(dst), "l"(src), "r"(sz));
}
#define CP_COMMIT() asm volatile("cp.async.commit_group;" ::: "memory")
#define CP_WAIT(n)  asm volatile("cp.async.wait_group %0;" :: "n"(n) : "memory")

__device__ __forceinline__ void ldsm4(uint32_t* r, uint32_t addr) {
    asm volatile("ldmatrix.sync.aligned.m8n8.x4.shared.b16 {%0,%1,%2,%3}, [%4];"
                 : "=r"(r[0]), "=r"(r[1]), "=r"(r[2]), "=r"(r[3]) : "r"(addr));
}
__device__ __forceinline__ void ldsm2(uint32_t* r, uint32_t addr) {
    asm volatile("ldmatrix.sync.aligned.m8n8.x2.shared.b16 {%0,%1}, [%2];"
                 : "=r"(r[0]), "=r"(r[1]) : "r"(addr));
}
__device__ __forceinline__ void mma16816(float* d, const uint32_t* a,
                                         const uint32_t* b) {
    asm volatile("mma.sync.aligned.m16n8k16.row.col.f32.bf16.bf16.f32 "
                 "{%0,%1,%2,%3}, {%4,%5,%6,%7}, {%8,%9}, {%0,%1,%2,%3};"
                 : "+f"(d[0]), "+f"(d[1]), "+f"(d[2]), "+f"(d[3])
                 : "r"(a[0]), "r"(a[1]), "r"(a[2]), "r"(a[3]),
                   "r"(b[0]), "r"(b[1]));
}
__device__ __forceinline__ uint32_t swz(int row, int chunk) {
    return (uint32_t)(row * 64 + ((chunk ^ ((row >> 1) & 3)) << 4));
}
__device__ __forceinline__ void split2(float v, bf16& h, bf16& l) {
    h = __float2bfloat16(v);
    l = __float2bfloat16(v - __bfloat162float(h));
}

// ------------------------- phase kernels -----------------------------------
__global__ void zero_kernel() {
    if (threadIdx.x < NEXP) g_cnt[threadIdx.x] = 0;
}

__global__ void route_kernel(const float* __restrict__ x,
                             const float* __restrict__ gw) {
    int warp = (blockIdx.x * blockDim.x + threadIdx.x) >> 5;
    int lane = threadIdx.x & 31;
    if (warp >= NTOK) return;
    const float* xr = x + (size_t)warp * DIMD;
    float xv[32];
#pragma unroll
    for (int i = 0; i < 32; i++) xv[i] = xr[i * 32 + lane];
    float logit[NEXP];
#pragma unroll
    for (int e = 0; e < NEXP; e++) {
        const float* g = gw + e * DIMD;
        float s = 0.f;
#pragma unroll
        for (int i = 0; i < 32; i++) s += xv[i] * g[i * 32 + lane];
#pragma unroll
        for (int o = 16; o; o >>= 1) s += __shfl_xor_sync(0xffffffffu, s, o);
        logit[e] = s;
    }
    float mx = logit[0];
#pragma unroll
    for (int e = 1; e < NEXP; e++) mx = fmaxf(mx, logit[e]);
    float p[NEXP], sum = 0.f;
#pragma unroll
    for (int e = 0; e < NEXP; e++) { p[e] = expf(logit[e] - mx); sum += p[e]; }
#pragma unroll
    for (int e = 0; e < NEXP; e++) p[e] /= sum;
    int i1 = 0;
#pragma unroll
    for (int e = 1; e < NEXP; e++) if (p[e] > p[i1]) i1 = e;
    int i2 = (i1 == 0) ? 1 : 0;
#pragma unroll
    for (int e = 0; e < NEXP; e++)
        if (e != i1 && e != i2 && p[e] > p[i2]) i2 = e;
    float d  = p[i1] + p[i2] + 1e-20f;
    float wa = p[i1] / d, wb = p[i2] / d;
    if (lane == 0) {
        int s1 = atomicAdd(&g_cnt[i1], 1);
        g_tok[i1 * CAP + s1] = warp; g_wt[i1 * CAP + s1] = wa;
        int s2 = atomicAdd(&g_cnt[i2], 1);
        g_tok[i2 * CAP + s2] = warp; g_wt[i2 * CAP + s2] = wb;
    }
}

__global__ void offsets_kernel() {
    if (threadIdx.x == 0) {
        int o = 0;
        for (int e = 0; e < NEXP; e++) { g_off[e] = o; o += g_cnt[e]; }
        g_off[NEXP] = o;
    }
}

// fp32 -> bf16 hi/lo split, vectorized by 4
__global__ void cvt_kernel(const float4* __restrict__ src,
                           uint2* __restrict__ hi, uint2* __restrict__ lo,
                           int n4) {
    int i = blockIdx.x * blockDim.x + threadIdx.x;
    if (i >= n4) return;
    float4 v = src[i];
    bf16 h0, h1, h2, h3, l0, l1, l2, l3;
    split2(v.x, h0, l0); split2(v.y, h1, l1);
    split2(v.z, h2, l2); split2(v.w, h3, l3);
    __nv_bfloat162 ha(h0, h1), hb(h2, h3), la(l0, l1), lb(l2, l3);
    uint2 H, L;
    H.x = *(const unsigned*)&ha; H.y = *(const unsigned*)&hb;
    L.x = *(const unsigned*)&la; L.y = *(const unsigned*)&lb;
    hi[i] = H; lo[i] = L;
}

// w1/w3 -> interleaved rows (2j, 2j+1) per logical row j (nMat = rows total
// across experts, i.e. NEXP*HID or HID). D fixed at DIMD.
__global__ void cvt_ilv_kernel(const float4* __restrict__ w1,
                               const float4* __restrict__ w3,
                               uint2* __restrict__ hi, uint2* __restrict__ lo,
                               int nRows) {
    const int D4 = DIMD / 4;
    int i = blockIdx.x * blockDim.x + threadIdx.x;   // over nRows * D4
    if (i >= nRows * D4) return;
    int r = i / D4, c = i % D4;
    int e = r / HID, j = r % HID;
    size_t d1 = ((size_t)(e * 2 * HID + 2 * j) * DIMD) / 4 + c;
    size_t d3 = d1 + D4;
#pragma unroll
    for (int s = 0; s < 2; s++) {
        float4 v = (s == 0) ? w1[i] : w3[i];
        bf16 h0, h1, h2, h3, l0, l1, l2, l3;
        split2(v.x, h0, l0); split2(v.y, h1, l1);
        split2(v.z, h2, l2); split2(v.w, h3, l3);
        __nv_bfloat162 ha(h0, h1), hb(h2, h3), la(l0, l1), lb(l2, l3);
        uint2 H, L;
        H.x = *(const unsigned*)&ha; H.y = *(const unsigned*)&hb;
        L.x = *(const unsigned*)&la; L.y = *(const unsigned*)&lb;
        size_t d = (s == 0) ? d1 : d3;
        hi[d] = H; lo[d] = L;
    }
}

__global__ void gather_kernel() {
    int e = blockIdx.y, i = blockIdx.x;
    int cnt = g_off[e + 1] - g_off[e];
    if (i >= cnt) return;
    int r = g_off[e] + i;
    int t = g_tok[e * CAP + i];
    const uint4* sh = (const uint4*)(g_xhi + (size_t)t * DIMD);
    const uint4* sl = (const uint4*)(g_xlo + (size_t)t * DIMD);
    uint4* dh = (uint4*)(g_gxhi + (size_t)r * DIMD);
    uint4* dl = (uint4*)(g_gxlo + (size_t)r * DIMD);
    int c = threadIdx.x;                 // 128 threads, 128 uint4/row
    dh[c] = sh[c]; dl[c] = sl[c];
    if (c == 0) { g_rowtok[r] = t; g_rowwt[r] = g_wt[e * CAP + i]; }
}

// ------------------------- HMMA grouped GEMM -------------------------------
// C[m,n] = sum_k Ahi*Bhi + Ahi*Blo + Alo*Bhi  (A row-major [*,K], B [N,K])
// mode bits: 1=grouped rows (g_off); 2=atomicAdd scatter via g_rowtok;
//            4=fused swiglu epilogue -> bf16 hi/lo (Hhi/Hlo); 8=apply g_rowwt.
__global__ __launch_bounds__(256, 2)
void hmma_gemm(const bf16* __restrict__ Ahi, const bf16* __restrict__ Alo,
               const bf16* __restrict__ Bhi, const bf16* __restrict__ Blo,
               float* __restrict__ C, bf16* __restrict__ Hhi,
               bf16* __restrict__ Hlo, int N, int K, long long strideB,
               int M0, int mode) {
    __shared__ __align__(1024) char smc[STG * 16384];
    uint32_t sb = smem_u32(smc);

    int e = blockIdx.z;
    int rs, re;
    if (mode & 1) { rs = g_off[e]; re = g_off[e + 1]; }
    else          { rs = 0;        re = M0; }
    int m0 = rs + blockIdx.y * TMg;
    if (m0 >= re) return;
    const bf16* bhi = Bhi + (size_t)e * strideB;
    const bf16* blo = Blo + (size_t)e * strideB;
    int n0 = blockIdx.x * TNg;

    int tid = threadIdx.x;
    int wid = tid >> 5, lane = tid & 31;
    int wm = wid & 1, wn = wid >> 1;

    const int KN = K / TKg;
    const int nch = 3 * KN;

    auto load_chunk = [&](int ch, int stage) {
        int p = (ch >= 2 * KN) ? 2 : (ch >= KN ? 1 : 0);
        int k0 = (ch - p * KN) * TKg;
        const bf16* Ap = (p == 2) ? Alo : Ahi;
        const bf16* Bp = (p == 1) ? blo : bhi;
        uint32_t sA = sb + stage * 16384;
        uint32_t sB = sA + 8192;
#pragma unroll
        for (int t = 0; t < 2; t++) {
            int u = tid + t * 256;
            int row = u >> 2, c = u & 3;
            int gr = m0 + row;
            int grc = (gr < re) ? gr : m0;
            const char* src = (const char*)(Ap + (size_t)grc * K + k0 + c * 8);
            cpa16(sA + swz(row, c), src, (gr < re) ? 16u : 0u);
        }
#pragma unroll
        for (int t = 0; t < 2; t++) {
            int u = tid + t * 256;
            int row = u >> 2, c = u & 3;
            int gn = n0 + row;
            int gnc = (gn < N) ? gn : 0;
            const char* src = (const char*)(Bp + (size_t)gnc * K + k0 + c * 8);
            cpa16(sB + swz(row, c), src, (gn < N) ? 16u : 0u);
        }
        CP_COMMIT();
    };

#pragma unroll
    for (int s = 0; s < STG - 1; s++) load_chunk(s, s);

    float acc[4][4][4];
#pragma unroll
    for (int a = 0; a < 4; a++)
#pragma unroll
        for (int b = 0; b < 4; b++)
#pragma unroll
            for (int c = 0; c < 4; c++) acc[a][b][c] = 0.f;

    for (int i = 0; i < nch; i++) {
        if (i + STG - 1 < nch) load_chunk(i + STG - 1, (i + STG - 1) % STG);
        else                   CP_COMMIT();
        CP_WAIT(STG - 1);
        __syncthreads();
        uint32_t sA = sb + (i % STG) * 16384;
        uint32_t sB = sA + 8192;
#pragma unroll
        for (int ks = 0; ks < 2; ks++) {
            uint32_t af[4][4], bfr[4][2];
#pragma unroll
            for (int mi = 0; mi < 4; mi++) {
                int row = wm * 64 + mi * 16 + (lane & 15);
                int c = ks * 2 + (lane >> 4);
                ldsm4(af[mi], sA + swz(row, c));
            }
#pragma unroll
            for (int nj = 0; nj < 4; nj++) {
                int row = wn * 32 + nj * 8 + (lane & 7);
                int c = ks * 2 + ((lane >> 3) & 1);
                ldsm2(bfr[nj], sB + swz(row, c));
            }
#pragma unroll
            for (int mi = 0; mi < 4; mi++)
#pragma unroll
                for (int nj = 0; nj < 4; nj++)
                    mma16816(acc[mi][nj], af[mi], bfr[nj]);
        }
        __syncthreads();
    }

    // ---------------- epilogue ----------------
    if (mode & 4) {
        // fused SwiGLU: even col = h (w1), odd col = g3 (w3); hidden = col>>1
#pragma unroll
        for (int mi = 0; mi < 4; mi++) {
#pragma unroll
            for (int h = 0; h < 2; h++) {
                int gr = m0 + wm * 64 + mi * 16 + (lane >> 2) + h * 8;
                if (gr >= re) continue;
                float w = (mode & 8) ? g_rowwt[gr] : 1.0f;
                size_t rowoff = (size_t)gr * HID;
#pragma unroll
                for (int nj = 0; nj < 4; nj++) {
                    int col = n0 + wn * 32 + nj * 8 + (lane & 3) * 2;
                    int hidx = col >> 1;
                    float hv = acc[mi][nj][h * 2 + 0];
                    float gv = acc[mi][nj][h * 2 + 1];
                    float v = w * (hv / (1.f + __expf(-hv))) * gv;
                    bf16 hb, lb;
                    split2(v, hb, lb);
                    Hhi[rowoff + hidx] = hb;
                    Hlo[rowoff + hidx] = lb;
                }
            }
        }
    } else {
#pragma unroll
        for (int mi = 0; mi < 4; mi++) {
            int r0 = m0 + wm * 64 + mi * 16 + (lane >> 2);
#pragma unroll
            for (int h = 0; h < 2; h++) {
                int gr = r0 + h * 8;
                if (gr >= re) continue;
                size_t crow = (mode & 2) ? (size_t)g_rowtok[gr] * N
                                         : (size_t)gr * N;
#pragma unroll
                for (int nj = 0; nj < 4; nj++) {
                    int col = n0 + wn * 32 + nj * 8 + (lane & 3) * 2;
                    if (col >= N) continue;
                    float v0 = acc[mi][nj][h * 2 + 0];
                    float v1 = acc[mi][nj][h * 2 + 1];
                    if (mode & 2) {
                        atomicAdd(&C[crow + col], v0);
                        atomicAdd(&C[crow + col + 1], v1);
                    } else {
                        *(float2*)&C[crow + col] = make_float2(v0, v1);
                    }
                }
            }
        }
    }
}

// ------------------------- launch ------------------------------------------
static void cvt(const void* src, void* hi, void* lo, size_t n) {
    int n4 = (int)(n / 4);
    cvt_kernel<<<(n4 + 255) / 256, 256>>>((const float4*)src, (uint2*)hi,
                                          (uint2*)lo, n4);
}

extern "C" void kernel_launch(void* const* d_in, const int* in_sizes, int n_in,
                              void* d_out, int out_size) {
    const float* x      = (const float*)d_in[0];
    const float* gate_w = (const float*)d_in[1];
    const float* w1     = (const float*)d_in[2];
    const float* w3     = (const float*)d_in[3];
    const float* w2     = (const float*)d_in[4];
    const float* sw1    = (const float*)d_in[5];
    const float* sw3    = (const float*)d_in[6];
    const float* sw2    = (const float*)d_in[7];
    float* out = (float*)d_out;

    void *xhi, *xlo, *gxhi, *gxlo, *hhi, *hlo;
    void *w13h, *w13l, *w2h, *w2l, *s13h, *s13l, *s2h, *s2l;
    cudaGetSymbolAddress(&xhi, g_xhi);    cudaGetSymbolAddress(&xlo, g_xlo);
    cudaGetSymbolAddress(&gxhi, g_gxhi);  cudaGetSymbolAddress(&gxlo, g_gxlo);
    cudaGetSymbolAddress(&hhi, g_hhi);    cudaGetSymbolAddress(&hlo, g_hlo);
    cudaGetSymbolAddress(&w13h, g_w13hi); cudaGetSymbolAddress(&w13l, g_w13lo);
    cudaGetSymbolAddress(&w2h, g_w2hi);   cudaGetSymbolAddress(&w2l, g_w2lo);
    cudaGetSymbolAddress(&s13h, g_s13hi); cudaGetSymbolAddress(&s13l, g_s13lo);
    cudaGetSymbolAddress(&s2h, g_s2hi);   cudaGetSymbolAddress(&s2l, g_s2lo);

    zero_kernel<<<1, 32>>>();
    route_kernel<<<NTOK / 8, 256>>>(x, gate_w);
    offsets_kernel<<<1, 1>>>();

    cvt(x, xhi, xlo, (size_t)NTOK * DIMD);
    gather_kernel<<<dim3(CAP, NEXP), 128>>>();

    {   // routed w1/w3 interleaved
        int n = NEXP * HID * (DIMD / 4);
        cvt_ilv_kernel<<<(n + 255) / 256, 256>>>((const float4*)w1,
            (const float4*)w3, (uint2*)w13h, (uint2*)w13l, NEXP * HID);
    }
    {   // shared sw1/sw3 interleaved
        int n = HID * (DIMD / 4);
        cvt_ilv_kernel<<<(n + 255) / 256, 256>>>((const float4*)sw1,
            (const float4*)sw3, (uint2*)s13h, (uint2*)s13l, HID);
    }
    cvt(w2,  w2h, w2l, (size_t)NEXP * DIMD * HID);
    cvt(sw2, s2h, s2l, (size_t)DIMD * HID);

    const int NT_I = 2 * HID / TNg;           // 43  (interleaved N = 5504)
    const int NT_D = DIMD / TNg;              // 8
    const int MT_T = NTOK / TMg;              // 64
    const int MT_C = CAP / TMg;               // 64

    // ---- shared expert: fused GEMM1+swiglu, then GEMM2 (direct store) ----
    hmma_gemm<<<dim3(NT_I, MT_T, 1), 256>>>(
        (const bf16*)xhi, (const bf16*)xlo, (const bf16*)s13h, (const bf16*)s13l,
        nullptr, (bf16*)hhi, (bf16*)hlo, 2 * HID, DIMD, 0, NTOK, 4);
    hmma_gemm<<<dim3(NT_D, MT_T, 1), 256>>>(
        (const bf16*)hhi, (const bf16*)hlo, (const bf16*)s2h, (const bf16*)s2l,
        out, nullptr, nullptr, DIMD, HID, 0, NTOK, 0);

    // ---- routed experts: fused grouped GEMM1+swiglu(+wt), GEMM2 scatter ---
    hmma_gemm<<<dim3(NT_I, MT_C, NEXP), 256>>>(
        (const bf16*)gxhi, (const bf16*)gxlo, (const bf16*)w13h, (const bf16*)w13l,
        nullptr, (bf16*)hhi, (bf16*)hlo, 2 * HID, DIMD,
        (long long)2 * HID * DIMD, 0, 1 | 4 | 8);
    hmma_gemm<<<dim3(NT_D, MT_C, NEXP), 256>>>(
        (const bf16*)hhi, (const bf16*)hlo, (const bf16*)w2h, (const bf16*)w2l,
        out, nullptr, nullptr, DIMD, HID, (long long)DIMD * HID, 0, 1 | 2);
}